// round 1
// baseline (speedup 1.0000x reference)
#include <cuda_runtime.h>
#include <cstdint>

// GaussianMixture NLL: N=65536 samples (2D), M=1024 mixture components.
// nll = -sum_n log( sum_m exp(wlog_m - qf(n,m)) )     (SPARSITY == 0)
//
// Strategy:
//  - prep kernel folds everything per-mixture into 6 constants, pre-scaled by
//    log2(e) and pre-negated so the hot loop is pure add/mul/fma + ex2.approx:
//      arg_log2 = wlogL + dx*(ng11L*dx + ng12_2L*dy) + dy*(ng22L*dy)
//    with ng* = -g* * log2e  =>  arg_log2 = log2e*(wlog - qf).
//  - hot kernel packs TWO mixtures per f32x2 instruction (sm_103a packed fp32),
//    params stored pair-interleaved in smem (48B per pair -> 3x LDS.128 broadcast).
//  - no max-subtraction needed: arg in ~[-22,-6] log2-units, safe for fp32.

#define M_MIX   1024
#define NPAIR   (M_MIX / 2)
#define TPB     256

__device__ float g_params[NPAIR * 12];   // scratch: pair-interleaved constants

typedef unsigned long long ull;

// ---------- packed f32x2 helpers ----------
__device__ __forceinline__ ull pack2(float a, float b) {
    ull r;
    unsigned int lo = __float_as_uint(a), hi = __float_as_uint(b);
    asm("mov.b64 %0, {%1, %2};" : "=l"(r) : "r"(lo), "r"(hi));
    return r;
}
__device__ __forceinline__ void unpack2(ull v, float& a, float& b) {
    unsigned int lo, hi;
    asm("mov.b64 {%0, %1}, %2;" : "=r"(lo), "=r"(hi) : "l"(v));
    a = __uint_as_float(lo);
    b = __uint_as_float(hi);
}
__device__ __forceinline__ ull addx2(ull a, ull b) {
    ull d; asm("add.rn.f32x2 %0, %1, %2;" : "=l"(d) : "l"(a), "l"(b)); return d;
}
__device__ __forceinline__ ull mulx2(ull a, ull b) {
    ull d; asm("mul.rn.f32x2 %0, %1, %2;" : "=l"(d) : "l"(a), "l"(b)); return d;
}
__device__ __forceinline__ ull fmax2_(ull a, ull b, ull c) {
    ull d; asm("fma.rn.f32x2 %0, %1, %2, %3;" : "=l"(d) : "l"(a), "l"(b), "l"(c)); return d;
}
__device__ __forceinline__ float ex2f(float x) {
    float y; asm("ex2.approx.f32 %0, %1;" : "=f"(y) : "f"(x)); return y;
}

// ---------- prep: per-mixture constants + log_softmax(w) ----------
__global__ void gmm_prep(const float* __restrict__ mu,
                         const float* __restrict__ sigma_log,
                         const float* __restrict__ theta,
                         const float* __restrict__ w,
                         float* __restrict__ out) {
    __shared__ float red[M_MIX];
    const int m = threadIdx.x;

    const float wi = w[m];

    // max reduction
    red[m] = wi;
    __syncthreads();
    for (int s = M_MIX / 2; s > 0; s >>= 1) {
        if (m < s) red[m] = fmaxf(red[m], red[m + s]);
        __syncthreads();
    }
    const float wmax = red[0];
    __syncthreads();

    // sum(exp) reduction
    red[m] = expf(wi - wmax);
    __syncthreads();
    for (int s = M_MIX / 2; s > 0; s >>= 1) {
        if (m < s) red[m] += red[m + s];
        __syncthreads();
    }
    const float logZ = wmax + logf(red[0]);

    const float sl0 = sigma_log[2 * m + 0];
    const float sl1 = sigma_log[2 * m + 1];
    const float a = expf(-2.0f * sl0);
    const float b = expf(-2.0f * sl1);
    const float c = cosf(theta[m]);
    const float s = sinf(theta[m]);

    const float g11 = a * c * c + b * s * s;
    const float g12 = (a - b) * c * s;
    const float g22 = a * s * s + b * c * c;
    const float wlog = wi - logZ - sl0 - sl1;

    const float L2E = 1.4426950408889634f;

    const int j = m >> 1;
    const int l = m & 1;
    float* P = &g_params[j * 12];
    P[0  + l] = -mu[2 * m + 0];       // nmux
    P[2  + l] = -mu[2 * m + 1];       // nmuy
    P[4  + l] = -g11 * L2E;           // ng11L
    P[6  + l] = -2.0f * g12 * L2E;    // ng12_2L
    P[8  + l] = -g22 * L2E;           // ng22L
    P[10 + l] =  wlog * L2E;          // wlogL

    if (m == 0) out[0] = 0.0f;        // re-zeroed every replay -> deterministic
}

// ---------- hot loop ----------
__global__ void __launch_bounds__(TPB) gmm_main(const float* __restrict__ sample,
                                                float* __restrict__ out,
                                                int N) {
    __shared__ __align__(16) float sp[NPAIR * 12];
    __shared__ float warpsum[TPB / 32];

    // cooperative param load (1536 float4)
    {
        const float4* gp  = (const float4*)g_params;
        float4*       sp4 = (float4*)sp;
        #pragma unroll
        for (int i = threadIdx.x; i < NPAIR * 3; i += TPB) sp4[i] = gp[i];
    }
    __syncthreads();

    const int idx = blockIdx.x * TPB + threadIdx.x;

    float nll_i = 0.0f;
    if (idx < N) {
        const float2 sv = ((const float2*)sample)[idx];
        const ull sxp = pack2(sv.x, sv.x);
        const ull syp = pack2(sv.y, sv.y);

        ull acc0 = 0ull;  // (0.f, 0.f)
        ull acc1 = 0ull;

        #pragma unroll 4
        for (int j = 0; j < NPAIR; ++j) {
            const ulonglong2* bp = (const ulonglong2*)(sp + j * 12);
            const ulonglong2 q0 = bp[0];   // {nmux_pair, nmuy_pair}
            const ulonglong2 q1 = bp[1];   // {ng11L_pair, ng12_2L_pair}
            const ulonglong2 q2 = bp[2];   // {ng22L_pair, wlogL_pair}

            const ull dx  = addx2(sxp, q0.x);
            const ull dy  = addx2(syp, q0.y);
            const ull t   = mulx2(q1.y, dy);
            const ull u   = fmax2_(q1.x, dx, t);     // -(L2E)(g11*dx + 2*g12*dy)
            const ull v   = mulx2(q2.x, dy);         // -(L2E) g22*dy
            const ull s0  = fmax2_(dy, v, q2.y);     // wlogL - L2E*g22*dy^2
            const ull arg = fmax2_(dx, u, s0);       // L2E*(wlog - qf)

            float a0, a1;
            unpack2(arg, a0, a1);
            const ull e = pack2(ex2f(a0), ex2f(a1));
            if (j & 1) acc1 = addx2(acc1, e);
            else       acc0 = addx2(acc0, e);
        }

        float r0, r1;
        unpack2(addx2(acc0, acc1), r0, r1);
        const float total = r0 + r1;                 // sum_m exp(wlog - qf)
        nll_i = -0.69314718055994531f * __log2f(total);
    }

    // warp reduce
    #pragma unroll
    for (int o = 16; o > 0; o >>= 1)
        nll_i += __shfl_xor_sync(0xffffffffu, nll_i, o);
    if ((threadIdx.x & 31) == 0) warpsum[threadIdx.x >> 5] = nll_i;
    __syncthreads();

    if (threadIdx.x < (TPB / 32)) {
        float v = warpsum[threadIdx.x];
        #pragma unroll
        for (int o = (TPB / 64); o > 0; o >>= 1)
            v += __shfl_xor_sync(0xffffffffu, v, o);
        if (threadIdx.x == 0) atomicAdd(out, v);
    }
}

extern "C" void kernel_launch(void* const* d_in, const int* in_sizes, int n_in,
                              void* d_out, int out_size) {
    const float* sample    = (const float*)d_in[0];
    const float* mu        = (const float*)d_in[1];
    const float* sigma_log = (const float*)d_in[2];
    const float* theta     = (const float*)d_in[3];
    const float* w         = (const float*)d_in[4];
    float* out = (float*)d_out;

    const int N = in_sizes[0] / 2;

    gmm_prep<<<1, M_MIX>>>(mu, sigma_log, theta, w, out);
    gmm_main<<<(N + TPB - 1) / TPB, TPB>>>(sample, out, N);
}

// round 3
// speedup vs baseline: 1.1766x; 1.1766x over previous
#include <cuda_runtime.h>
#include <cstdint>

// GaussianMixture NLL: N=65536 samples (2D), M=1024 mixtures.  SPARSITY == 0.
// nll = -sum_n log( sum_m exp(wlog_m - qf(n,m)) )
//
// v2 strategy (re-bench after infra failure):
//  - expanded quadratic: arg_log2 = c0*x^2 + c1*xy + c2*y^2 + c3*x + c4*y + c5
//    (all constants pre-scaled by log2(e), signs folded) -> 5 packed fma + acc.
//  - packed f32x2 (sm_103a): 2 mixtures per instruction; params pair-interleaved
//    in smem, 48B/pair -> 3 broadcast LDS.128 shared by 4 samples.
//  - each thread: 4 samples x 128 mixture-pairs (one quarter of M) -> 4-way ILP,
//    smem traffic /4.  Quarters recombined through a small smem transpose.
//  - TPB=224, 224 samples/block, grid=293 <= 2*148 CTAs -> ~99% wave balance.
//  - no logsumexp max needed: arg in ~[-19,-7] log2-units, fp32-safe.

#define M_MIX   1024
#define NPAIR   (M_MIX / 2)      // 512
#define QPAIRS  (NPAIR / 4)      // 128 pairs per quarter
#define TPB     224
#define SAMP_PER_BLK  224

__device__ float g_params[NPAIR * 12];   // pair-interleaved coefficients

typedef unsigned long long ull;

// ---------- packed f32x2 helpers ----------
__device__ __forceinline__ ull pack2(float a, float b) {
    ull r;
    unsigned int lo = __float_as_uint(a), hi = __float_as_uint(b);
    asm("mov.b64 %0, {%1, %2};" : "=l"(r) : "r"(lo), "r"(hi));
    return r;
}
__device__ __forceinline__ void unpack2(ull v, float& a, float& b) {
    unsigned int lo, hi;
    asm("mov.b64 {%0, %1}, %2;" : "=r"(lo), "=r"(hi) : "l"(v));
    a = __uint_as_float(lo);
    b = __uint_as_float(hi);
}
__device__ __forceinline__ ull addx2(ull a, ull b) {
    ull d; asm("add.rn.f32x2 %0, %1, %2;" : "=l"(d) : "l"(a), "l"(b)); return d;
}
__device__ __forceinline__ ull fmax2_(ull a, ull b, ull c) {
    ull d; asm("fma.rn.f32x2 %0, %1, %2, %3;" : "=l"(d) : "l"(a), "l"(b), "l"(c)); return d;
}
__device__ __forceinline__ float ex2f(float x) {
    float y; asm("ex2.approx.f32 %0, %1;" : "=f"(y) : "f"(x)); return y;
}

// ---------- prep: log_softmax(w) + polynomial coefficients ----------
__global__ void gmm_prep(const float* __restrict__ mu,
                         const float* __restrict__ sigma_log,
                         const float* __restrict__ theta,
                         const float* __restrict__ w,
                         float* __restrict__ out) {
    __shared__ float red[M_MIX];
    const int m = threadIdx.x;

    const float wi = w[m];

    // max reduction
    red[m] = wi;
    __syncthreads();
    for (int s = M_MIX / 2; s > 0; s >>= 1) {
        if (m < s) red[m] = fmaxf(red[m], red[m + s]);
        __syncthreads();
    }
    const float wmax = red[0];
    __syncthreads();

    // sum(exp) reduction
    red[m] = expf(wi - wmax);
    __syncthreads();
    for (int s = M_MIX / 2; s > 0; s >>= 1) {
        if (m < s) red[m] += red[m + s];
        __syncthreads();
    }
    const float logZ = wmax + logf(red[0]);

    const float sl0 = sigma_log[2 * m + 0];
    const float sl1 = sigma_log[2 * m + 1];
    const float a = expf(-2.0f * sl0);
    const float b = expf(-2.0f * sl1);
    const float c = cosf(theta[m]);
    const float s = sinf(theta[m]);

    const float g11 = a * c * c + b * s * s;
    const float g12 = (a - b) * c * s;
    const float g22 = a * s * s + b * c * c;
    const float wlog = wi - logZ - sl0 - sl1;

    const float mx = mu[2 * m + 0];
    const float my = mu[2 * m + 1];

    const float L2E = 1.4426950408889634f;

    const float c0 = -L2E * g11;
    const float c1 = -L2E * 2.0f * g12;
    const float c2 = -L2E * g22;
    const float c3 =  L2E * 2.0f * (g11 * mx + g12 * my);
    const float c4 =  L2E * 2.0f * (g12 * mx + g22 * my);
    const float c5 =  L2E * (wlog - (g11 * mx * mx + 2.0f * g12 * mx * my + g22 * my * my));

    const int j = m >> 1;
    const int l = m & 1;
    float* P = &g_params[j * 12];
    P[0  + l] = c0;
    P[2  + l] = c1;
    P[4  + l] = c2;
    P[6  + l] = c3;
    P[8  + l] = c4;
    P[10 + l] = c5;

    if (m == 0) out[0] = 0.0f;        // re-zeroed every replay -> deterministic
}

// ---------- hot loop ----------
__global__ void __launch_bounds__(TPB) gmm_main(const float* __restrict__ sample,
                                                float* __restrict__ out,
                                                int N) {
    __shared__ __align__(16) float sp[NPAIR * 12];    // 24 KB coefficients
    __shared__ float partial[4 * TPB];                // quarter partial sums
    __shared__ float warpsum[TPB / 32];

    // cooperative param load (1536 float4)
    {
        const float4* gp  = (const float4*)g_params;
        float4*       sp4 = (float4*)sp;
        for (int i = threadIdx.x; i < NPAIR * 3; i += TPB) sp4[i] = gp[i];
    }
    __syncthreads();

    const int q    = threadIdx.x / 56;        // mixture quarter  (0..3)
    const int sg   = threadIdx.x % 56;        // sample group     (0..55)
    const int base = blockIdx.x * SAMP_PER_BLK;
    const int s0   = base + sg * 4;

    // per-sample packed monomials: x^2, xy, y^2, x, y
    ull xxp[4], xyp[4], yyp[4], xp[4], yp[4], acc[4];
    #pragma unroll
    for (int k = 0; k < 4; ++k) {
        const int idx = s0 + k;
        float x = 0.0f, y = 0.0f;
        if (idx < N) {
            const float2 sv = ((const float2*)sample)[idx];
            x = sv.x; y = sv.y;
        }
        const float xx = x * x, xy = x * y, yy = y * y;
        xxp[k] = pack2(xx, xx);
        xyp[k] = pack2(xy, xy);
        yyp[k] = pack2(yy, yy);
        xp[k]  = pack2(x, x);
        yp[k]  = pack2(y, y);
        acc[k] = 0ull;
    }

    const float* qp = sp + q * QPAIRS * 12;

    #pragma unroll 2
    for (int j = 0; j < QPAIRS; ++j) {
        const ulonglong2* bp = (const ulonglong2*)(qp + j * 12);
        const ulonglong2 q0 = bp[0];   // {c0_pair, c1_pair}
        const ulonglong2 q1 = bp[1];   // {c2_pair, c3_pair}
        const ulonglong2 q2 = bp[2];   // {c4_pair, c5_pair}

        #pragma unroll
        for (int k = 0; k < 4; ++k) {
            ull t = fmax2_(q2.x, yp[k],  q2.y);   // c4*y  + c5
            t     = fmax2_(q1.y, xp[k],  t);      // +c3*x
            t     = fmax2_(q1.x, yyp[k], t);      // +c2*y^2
            t     = fmax2_(q0.y, xyp[k], t);      // +c1*xy
            t     = fmax2_(q0.x, xxp[k], t);      // +c0*x^2   = L2E*(wlog-qf)
            float a0, a1;
            unpack2(t, a0, a1);
            const ull e = pack2(ex2f(a0), ex2f(a1));
            acc[k] = addx2(acc[k], e);
        }
    }

    #pragma unroll
    for (int k = 0; k < 4; ++k) {
        float r0, r1;
        unpack2(acc[k], r0, r1);
        partial[q * TPB + sg * 4 + k] = r0 + r1;
    }
    __syncthreads();

    // combine quarters; one sample per thread
    float nll_i = 0.0f;
    const int sidx = base + threadIdx.x;
    if (threadIdx.x < SAMP_PER_BLK && sidx < N) {
        const float tot = partial[threadIdx.x]
                        + partial[TPB     + threadIdx.x]
                        + partial[2 * TPB + threadIdx.x]
                        + partial[3 * TPB + threadIdx.x];
        nll_i = -0.69314718055994531f * __log2f(tot);
    }

    // block reduce
    #pragma unroll
    for (int o = 16; o > 0; o >>= 1)
        nll_i += __shfl_xor_sync(0xffffffffu, nll_i, o);
    if ((threadIdx.x & 31) == 0) warpsum[threadIdx.x >> 5] = nll_i;
    __syncthreads();

    if (threadIdx.x == 0) {
        float v = 0.0f;
        #pragma unroll
        for (int i = 0; i < TPB / 32; ++i) v += warpsum[i];
        atomicAdd(out, v);
    }
}

extern "C" void kernel_launch(void* const* d_in, const int* in_sizes, int n_in,
                              void* d_out, int out_size) {
    const float* sample    = (const float*)d_in[0];
    const float* mu        = (const float*)d_in[1];
    const float* sigma_log = (const float*)d_in[2];
    const float* theta     = (const float*)d_in[3];
    const float* w         = (const float*)d_in[4];
    float* out = (float*)d_out;

    const int N = in_sizes[0] / 2;
    const int grid = (N + SAMP_PER_BLK - 1) / SAMP_PER_BLK;

    gmm_prep<<<1, M_MIX>>>(mu, sigma_log, theta, w, out);
    gmm_main<<<grid, TPB>>>(sample, out, N);
}

// round 4
// speedup vs baseline: 1.2558x; 1.0673x over previous
#include <cuda_runtime.h>
#include <cstdint>

// GaussianMixture NLL: N=65536 samples (2D), M=1024 mixtures.  SPARSITY == 0.
// nll = -sum_n log( sum_m exp(wlog_m - qf(n,m)) )
//
// v3: v2 polynomial/f32x2 scheme, but 2 samples/thread -> grid=586 (~4 CTA/SM,
//     28 warps/SM) to saturate the MUFU (ex2) pipe, which is the binding
//     resource (floor ~28.4K cyc). Prep kernel rewritten with shuffle
//     reductions + fast-math.

#define M_MIX   1024
#define NPAIR   (M_MIX / 2)      // 512
#define QPAIRS  (NPAIR / 4)      // 128 pairs per quarter
#define TPB     224
#define SPT     2                // samples per thread
#define SAMP_PER_BLK  112        // 56 groups * 2

__device__ float g_params[NPAIR * 12];   // pair-interleaved coefficients

typedef unsigned long long ull;

// ---------- packed f32x2 helpers ----------
__device__ __forceinline__ ull pack2(float a, float b) {
    ull r;
    unsigned int lo = __float_as_uint(a), hi = __float_as_uint(b);
    asm("mov.b64 %0, {%1, %2};" : "=l"(r) : "r"(lo), "r"(hi));
    return r;
}
__device__ __forceinline__ void unpack2(ull v, float& a, float& b) {
    unsigned int lo, hi;
    asm("mov.b64 {%0, %1}, %2;" : "=r"(lo), "=r"(hi) : "l"(v));
    a = __uint_as_float(lo);
    b = __uint_as_float(hi);
}
__device__ __forceinline__ ull addx2(ull a, ull b) {
    ull d; asm("add.rn.f32x2 %0, %1, %2;" : "=l"(d) : "l"(a), "l"(b)); return d;
}
__device__ __forceinline__ ull fmax2_(ull a, ull b, ull c) {
    ull d; asm("fma.rn.f32x2 %0, %1, %2, %3;" : "=l"(d) : "l"(a), "l"(b), "l"(c)); return d;
}
__device__ __forceinline__ float ex2f(float x) {
    float y; asm("ex2.approx.f32 %0, %1;" : "=f"(y) : "f"(x)); return y;
}

// ---------- prep: log_softmax(w) + polynomial coefficients ----------
__global__ void gmm_prep(const float* __restrict__ mu,
                         const float* __restrict__ sigma_log,
                         const float* __restrict__ theta,
                         const float* __restrict__ w,
                         float* __restrict__ out) {
    __shared__ float red[32];
    const int m    = threadIdx.x;
    const int lane = m & 31;
    const int wid  = m >> 5;

    const float wi = w[m];

    // block max via shuffle
    float v = wi;
    #pragma unroll
    for (int o = 16; o > 0; o >>= 1) v = fmaxf(v, __shfl_xor_sync(~0u, v, o));
    if (lane == 0) red[wid] = v;
    __syncthreads();
    float wmax = red[lane & 31];
    #pragma unroll
    for (int o = 16; o > 0; o >>= 1) wmax = fmaxf(wmax, __shfl_xor_sync(~0u, wmax, o));
    wmax = __shfl_sync(~0u, wmax, 0);
    __syncthreads();

    // block sum(exp) via shuffle
    float e = __expf(wi - wmax);
    #pragma unroll
    for (int o = 16; o > 0; o >>= 1) e += __shfl_xor_sync(~0u, e, o);
    if (lane == 0) red[wid] = e;
    __syncthreads();
    float esum = red[lane & 31];
    #pragma unroll
    for (int o = 16; o > 0; o >>= 1) esum += __shfl_xor_sync(~0u, esum, o);
    esum = __shfl_sync(~0u, esum, 0);

    const float logZ = wmax + __logf(esum);

    const float sl0 = sigma_log[2 * m + 0];
    const float sl1 = sigma_log[2 * m + 1];
    const float a = __expf(-2.0f * sl0);
    const float b = __expf(-2.0f * sl1);
    float s, c;
    __sincosf(theta[m], &s, &c);

    const float g11 = a * c * c + b * s * s;
    const float g12 = (a - b) * c * s;
    const float g22 = a * s * s + b * c * c;
    const float wlog = wi - logZ - sl0 - sl1;

    const float mx = mu[2 * m + 0];
    const float my = mu[2 * m + 1];

    const float L2E = 1.4426950408889634f;

    const float c0 = -L2E * g11;
    const float c1 = -L2E * 2.0f * g12;
    const float c2 = -L2E * g22;
    const float c3 =  L2E * 2.0f * (g11 * mx + g12 * my);
    const float c4 =  L2E * 2.0f * (g12 * mx + g22 * my);
    const float c5 =  L2E * (wlog - (g11 * mx * mx + 2.0f * g12 * mx * my + g22 * my * my));

    const int j = m >> 1;
    const int l = m & 1;
    float* P = &g_params[j * 12];
    P[0  + l] = c0;
    P[2  + l] = c1;
    P[4  + l] = c2;
    P[6  + l] = c3;
    P[8  + l] = c4;
    P[10 + l] = c5;

    if (m == 0) out[0] = 0.0f;        // re-zeroed every replay -> deterministic
}

// ---------- hot loop ----------
__global__ void __launch_bounds__(TPB, 4) gmm_main(const float* __restrict__ sample,
                                                   float* __restrict__ out,
                                                   int N) {
    __shared__ __align__(16) float sp[NPAIR * 12];    // 24 KB coefficients
    __shared__ float partial[4 * SAMP_PER_BLK];       // quarter partial sums
    __shared__ float warpsum[TPB / 32];

    // cooperative param load (1536 float4)
    {
        const float4* gp  = (const float4*)g_params;
        float4*       sp4 = (float4*)sp;
        for (int i = threadIdx.x; i < NPAIR * 3; i += TPB) sp4[i] = gp[i];
    }
    __syncthreads();

    const int q    = threadIdx.x / 56;        // mixture quarter  (0..3)
    const int sg   = threadIdx.x % 56;        // sample group     (0..55)
    const int base = blockIdx.x * SAMP_PER_BLK;
    const int s0   = base + sg * SPT;

    // per-sample packed monomials: x^2, xy, y^2, x, y
    ull xxp[SPT], xyp[SPT], yyp[SPT], xp[SPT], yp[SPT], acc[SPT];
    #pragma unroll
    for (int k = 0; k < SPT; ++k) {
        const int idx = s0 + k;
        float x = 0.0f, y = 0.0f;
        if (idx < N) {
            const float2 sv = ((const float2*)sample)[idx];
            x = sv.x; y = sv.y;
        }
        const float xx = x * x, xy = x * y, yy = y * y;
        xxp[k] = pack2(xx, xx);
        xyp[k] = pack2(xy, xy);
        yyp[k] = pack2(yy, yy);
        xp[k]  = pack2(x, x);
        yp[k]  = pack2(y, y);
        acc[k] = 0ull;
    }

    const float* qp = sp + q * QPAIRS * 12;

    #pragma unroll 2
    for (int j = 0; j < QPAIRS; ++j) {
        const ulonglong2* bp = (const ulonglong2*)(qp + j * 12);
        const ulonglong2 q0 = bp[0];   // {c0_pair, c1_pair}
        const ulonglong2 q1 = bp[1];   // {c2_pair, c3_pair}
        const ulonglong2 q2 = bp[2];   // {c4_pair, c5_pair}

        #pragma unroll
        for (int k = 0; k < SPT; ++k) {
            ull t = fmax2_(q2.x, yp[k],  q2.y);   // c4*y  + c5
            t     = fmax2_(q1.y, xp[k],  t);      // +c3*x
            t     = fmax2_(q1.x, yyp[k], t);      // +c2*y^2
            t     = fmax2_(q0.y, xyp[k], t);      // +c1*xy
            t     = fmax2_(q0.x, xxp[k], t);      // +c0*x^2   = L2E*(wlog-qf)
            float a0, a1;
            unpack2(t, a0, a1);
            const ull e = pack2(ex2f(a0), ex2f(a1));
            acc[k] = addx2(acc[k], e);
        }
    }

    #pragma unroll
    for (int k = 0; k < SPT; ++k) {
        float r0, r1;
        unpack2(acc[k], r0, r1);
        partial[q * SAMP_PER_BLK + sg * SPT + k] = r0 + r1;
    }
    __syncthreads();

    // combine quarters; one sample per thread
    float nll_i = 0.0f;
    const int sidx = base + threadIdx.x;
    if (threadIdx.x < SAMP_PER_BLK && sidx < N) {
        const float tot = partial[threadIdx.x]
                        + partial[SAMP_PER_BLK     + threadIdx.x]
                        + partial[2 * SAMP_PER_BLK + threadIdx.x]
                        + partial[3 * SAMP_PER_BLK + threadIdx.x];
        nll_i = -0.69314718055994531f * __log2f(tot);
    }

    // block reduce
    #pragma unroll
    for (int o = 16; o > 0; o >>= 1)
        nll_i += __shfl_xor_sync(0xffffffffu, nll_i, o);
    if ((threadIdx.x & 31) == 0) warpsum[threadIdx.x >> 5] = nll_i;
    __syncthreads();

    if (threadIdx.x == 0) {
        float v = 0.0f;
        #pragma unroll
        for (int i = 0; i < TPB / 32; ++i) v += warpsum[i];
        atomicAdd(out, v);
    }
}

extern "C" void kernel_launch(void* const* d_in, const int* in_sizes, int n_in,
                              void* d_out, int out_size) {
    const float* sample    = (const float*)d_in[0];
    const float* mu        = (const float*)d_in[1];
    const float* sigma_log = (const float*)d_in[2];
    const float* theta     = (const float*)d_in[3];
    const float* w         = (const float*)d_in[4];
    float* out = (float*)d_out;

    const int N = in_sizes[0] / 2;
    const int grid = (N + SAMP_PER_BLK - 1) / SAMP_PER_BLK;

    gmm_prep<<<1, M_MIX>>>(mu, sigma_log, theta, w, out);
    gmm_main<<<grid, TPB>>>(sample, out, N);
}